// round 13
// baseline (speedup 1.0000x reference)
#include <cuda_runtime.h>

#define BATCH 4096
#define NCLS  10000
#define DIM   256
#define ALPHA 0.5f
#define CAP   64   // per-class row-list capacity (overflow handled exactly)

// Scratch (allocation-free: __device__ globals).
// g_cnt starts zeroed (static init); K2 re-zeroes ONLY touched classes
// (untouched are already 0) -> no zero kernel.
__device__ int g_cnt[NCLS];         // per-class sample count
__device__ int g_label[BATCH];      // decoded label per row (overflow fallback)
__device__ int g_rows[NCLS * CAP];  // per-class row index list (8B aligned rows)

// ---------------------------------------------------------------------------
// K1: ONE WARP PER ROW, DEPTH-2 software pipeline. Zero barriers, zero shared
// memory, zero cross-warp coordination. 4096 warps in 1024 blocks of 128
// threads (finer SM load balance than 512x256).
// Each iteration covers 2 KB (4 float4/lane); TWO iterations are kept in
// flight (4 KB/warp, 8 LDG.128 outstanding) while a third is tested via
// __ballot_sync. Overshoot ~4 KB/row beyond the hit; expected read
// ~24 KB per 40 KB row.
// ---------------------------------------------------------------------------
__global__ __launch_bounds__(128, 8)
void scan_loss_kernel(const float* __restrict__ onehot,
                      const float* __restrict__ feat,
                      const float* __restrict__ centers,
                      float* __restrict__ loss_out) {
    const int lane = threadIdx.x & 31;
    const int b    = blockIdx.x * 4 + (threadIdx.x >> 5);  // row for this warp

    const float4* row = reinterpret_cast<const float4*>(onehot + (size_t)b * NCLS);
    const int NV4 = NCLS / 4;            // 2500 float4
    const int PER_IT = 128;              // float4 per iteration (32 lanes x 4)
    const int NIT = (NV4 + PER_IT - 1) / PER_IT;  // 20

    float4 buf0[4], buf1[4];
    // prime the pipeline: iterations 0 and 1
    #pragma unroll
    for (int k = 0; k < 4; ++k) {
        int i = lane + 32 * k;
        buf0[k] = (i < NV4) ? row[i] : make_float4(0.f, 0.f, 0.f, 0.f);
    }
    #pragma unroll
    for (int k = 0; k < 4; ++k) {
        int i = PER_IT + lane + 32 * k;
        buf1[k] = (i < NV4) ? row[i] : make_float4(0.f, 0.f, 0.f, 0.f);
    }

    int label = -1;
    #pragma unroll 1
    for (int it = 0; it < NIT; ++it) {
        // issue iteration it+2 BEFORE testing iteration it (depth-2)
        float4 nxt[4];
        if (it + 2 < NIT) {
            #pragma unroll
            for (int k = 0; k < 4; ++k) {
                int i = (it + 2) * PER_IT + lane + 32 * k;
                nxt[k] = (i < NV4) ? row[i] : make_float4(0.f, 0.f, 0.f, 0.f);
            }
        }
        // test iteration it (in buf0)
        int found = -1;
        const int base = it * PER_IT;
        #pragma unroll
        for (int k = 0; k < 4; ++k) {
            int i = base + lane + 32 * k;
            if (buf0[k].x != 0.f)      found = 4 * i + 0;
            else if (buf0[k].y != 0.f) found = 4 * i + 1;
            else if (buf0[k].z != 0.f) found = 4 * i + 2;
            else if (buf0[k].w != 0.f) found = 4 * i + 3;
        }
        unsigned m = __ballot_sync(0xFFFFFFFFu, found >= 0);
        if (m) {
            const int src = __ffs(m) - 1;          // exactly one lane finds it
            if (lane == src) {
                g_label[b] = found;
                int slot = atomicAdd(&g_cnt[found], 1);
                if (slot < CAP) g_rows[found * CAP + slot] = b;
            }
            label = __shfl_sync(0xFFFFFFFFu, found, src);
            break;
        }
        #pragma unroll
        for (int k = 0; k < 4; ++k) { buf0[k] = buf1[k]; buf1[k] = nxt[k]; }
    }

    // loss vs OLD centers: lane owns dims [lane*8, lane*8+8)
    const float4* frow = reinterpret_cast<const float4*>(feat + (size_t)b * DIM);
    const float4* crow = reinterpret_cast<const float4*>(centers + (size_t)label * DIM);
    float4 fA = frow[lane * 2], fB = frow[lane * 2 + 1];
    float4 cA = crow[lane * 2], cB = crow[lane * 2 + 1];
    float dx, sq;
    dx = fA.x - cA.x; sq  = dx * dx;
    dx = fA.y - cA.y; sq += dx * dx;
    dx = fA.z - cA.z; sq += dx * dx;
    dx = fA.w - cA.w; sq += dx * dx;
    dx = fB.x - cB.x; sq += dx * dx;
    dx = fB.y - cB.y; sq += dx * dx;
    dx = fB.z - cB.z; sq += dx * dx;
    dx = fB.w - cB.w; sq += dx * dx;
    #pragma unroll
    for (int off = 16; off > 0; off >>= 1)
        sq += __shfl_down_sync(0xFFFFFFFFu, sq, off);
    if (lane == 0) loss_out[b] = sq;
}

// ---------------------------------------------------------------------------
// K2: one WARP per class row (measured best). ALL lanes load g_cnt[c]
// (broadcast LDG). n==0 fast path (66% of classes): verbatim copy, no
// counter store. n>=1: lane 0 cleans counter after the warp-wide load (warp
// program order -> race-free, no barriers); up to 4 independent feat
// gathers in flight.
// ---------------------------------------------------------------------------
__global__ __launch_bounds__(256)
void scale_gather_kernel(const float* __restrict__ centers,
                         const float* __restrict__ feat,
                         float* __restrict__ out_centers) {
    const int c    = (blockIdx.x * blockDim.x + threadIdx.x) >> 5;  // class; grid exact
    const int lane = threadIdx.x & 31;

    const int n = g_cnt[c];
    const int2 r01 = *reinterpret_cast<const int2*>(&g_rows[c * CAP]);
    const float4* crow = reinterpret_cast<const float4*>(centers) + (size_t)c * 64;
    float4 a0 = crow[lane];
    float4 a1 = crow[lane + 32];
    float4* orow = reinterpret_cast<float4*>(out_centers) + (size_t)c * 64;

    if (n == 0) {  // 66% of classes: pure copy, counter already zero
        orow[lane]      = a0;
        orow[lane + 32] = a1;
        return;
    }

    if (lane == 0) g_cnt[c] = 0;  // warp program order after the load: race-free

    const float fn = (float)n;
    const float s = __fdividef(ALPHA, fn + 1.0f);
    const float k = 1.0f - fn * s;
    a0.x *= k; a0.y *= k; a0.z *= k; a0.w *= k;
    a1.x *= k; a1.y *= k; a1.z *= k; a1.w *= k;

    const float4* feat4 = reinterpret_cast<const float4*>(feat);

    float4 f00 = feat4[(size_t)r01.x * 64 + lane];
    float4 f01 = feat4[(size_t)r01.x * 64 + lane + 32];
    float4 f10 = make_float4(0.f, 0.f, 0.f, 0.f);
    float4 f11 = make_float4(0.f, 0.f, 0.f, 0.f);
    if (n >= 2) {
        f10 = feat4[(size_t)r01.y * 64 + lane];
        f11 = feat4[(size_t)r01.y * 64 + lane + 32];
    }
    a0.x += s * (f00.x + f10.x); a0.y += s * (f00.y + f10.y);
    a0.z += s * (f00.z + f10.z); a0.w += s * (f00.w + f10.w);
    a1.x += s * (f01.x + f11.x); a1.y += s * (f01.y + f11.y);
    a1.z += s * (f01.z + f11.z); a1.w += s * (f01.w + f11.w);

    if (n > 2) {
        const int m = (n <= CAP) ? n : CAP;
        #pragma unroll 1
        for (int j = 2; j < m; ++j) {
            int bj = g_rows[c * CAP + j];
            float4 g0 = feat4[(size_t)bj * 64 + lane];
            float4 g1 = feat4[(size_t)bj * 64 + lane + 32];
            a0.x += s * g0.x; a0.y += s * g0.y; a0.z += s * g0.z; a0.w += s * g0.w;
            a1.x += s * g1.x; a1.y += s * g1.y; a1.z += s * g1.z; a1.w += s * g1.w;
        }
        if (n > CAP) {
            // exhaustive fallback (statistically unreachable; exact)
            #pragma unroll 1
            for (int bb = 0; bb < BATCH; ++bb) {
                if (g_label[bb] == c) {
                    bool seen = false;
                    for (int j = 0; j < CAP; ++j)
                        if (g_rows[c * CAP + j] == bb) { seen = true; break; }
                    if (!seen) {
                        float4 g0 = feat4[(size_t)bb * 64 + lane];
                        float4 g1 = feat4[(size_t)bb * 64 + lane + 32];
                        a0.x += s * g0.x; a0.y += s * g0.y;
                        a0.z += s * g0.z; a0.w += s * g0.w;
                        a1.x += s * g1.x; a1.y += s * g1.y;
                        a1.z += s * g1.z; a1.w += s * g1.w;
                    }
                }
            }
        }
    }

    orow[lane]      = a0;
    orow[lane + 32] = a1;
}

// ---------------------------------------------------------------------------
extern "C" void kernel_launch(void* const* d_in, const int* in_sizes, int n_in,
                              void* d_out, int out_size) {
    const float* feat    = (const float*)d_in[0];  // [4096, 256]
    const float* onehot  = (const float*)d_in[1];  // [4096, 10000]
    const float* centers = (const float*)d_in[2];  // [10000, 256]

    float* loss_out    = (float*)d_out;            // [4096]
    float* centers_out = (float*)d_out + BATCH;    // [10000, 256]

    // 4096 rows, one warp each -> 1024 blocks of 4 warps (exact)
    scan_loss_kernel<<<BATCH / 4, 128>>>(onehot, feat, centers, loss_out);
    // 10000 classes, one warp each -> 1250 blocks of 256 threads (exact)
    scale_gather_kernel<<<NCLS * 32 / 256, 256>>>(centers, feat, centers_out);
}